// round 17
// baseline (speedup 1.0000x reference)
#include <cuda_runtime.h>
#include <cuda_fp16.h>
#include <math.h>
#include <stdint.h>

#define B_ 4
#define T_ 2048
#define C_ 768
#define H_ 16
#define D_ 48

// ---------------- scratch (static device globals; no allocation) ----------------
__device__ __half g_qh[B_*H_*T_*D_];   // Q, roped, fp16, [B,H,T,D]
__device__ __half g_kh[B_*H_*T_*D_];   // K, roped, fp16, [B,H,T,D]
__device__ __half g_vh[B_*H_*T_*D_];   // V, fp16, TRANSPOSED [B,H,D,T]
__device__ __half g_ctx[B_*T_*C_];     // attention output, fp16, [B,T,C]
__device__ float  g_cos[T_*D_];
__device__ float  g_sin[T_*D_];
__device__ __half g_xh[B_*T_*C_];      // X,  fp16
__device__ __half g_wqh[C_*C_];        // Wq, fp16
__device__ __half g_wkh[C_*C_];
__device__ __half g_wvh[C_*C_];
__device__ __half g_woh[C_*C_];

// ---------------- helpers -------------------------------------------------------
// d += a * b   (m16n8k16, fp16 inputs, f32 accum)
__device__ __forceinline__ void mma_f16(float* d, const uint32_t* a, const uint32_t* b) {
    asm volatile(
        "mma.sync.aligned.m16n8k16.row.col.f32.f16.f16.f32 "
        "{%0,%1,%2,%3}, {%4,%5,%6,%7}, {%8,%9}, {%0,%1,%2,%3};\n"
        : "+f"(d[0]), "+f"(d[1]), "+f"(d[2]), "+f"(d[3])
        : "r"(a[0]), "r"(a[1]), "r"(a[2]), "r"(a[3]),
          "r"(b[0]), "r"(b[1]));
}

__device__ __forceinline__ uint32_t ldsm_u32(const __half* p) {
    return *(const uint32_t*)p;
}

// pack (lo,hi) to f16x2 and take 2^x of both halves
__device__ __forceinline__ uint32_t exp2_f16x2(float lo, float hi) {
    uint32_t r;
    asm("{.reg .b32 t;\n\t"
        "cvt.rn.f16x2.f32 t, %2, %1;\n\t"
        "ex2.approx.f16x2 %0, t;}"
        : "=r"(r) : "f"(lo), "f"(hi));
    return r;
}

__device__ __forceinline__ void cp16(uint32_t smem_dst, const void* gmem_src) {
    asm volatile("cp.async.cg.shared.global [%0], [%1], 16;\n"
                 :: "r"(smem_dst), "l"(gmem_src));
}
__device__ __forceinline__ void cp_commit() {
    asm volatile("cp.async.commit_group;\n" ::: "memory");
}
template <int N>
__device__ __forceinline__ void cp_wait() {
    asm volatile("cp.async.wait_group %0;\n" :: "n"(N) : "memory");
}

#define LOG2E 1.44269504088896f

// ---------------- prep: fp32 -> fp16 for X + 4 weight matrices (one launch) -----
__global__ void f2h_all_kernel(const float* __restrict__ X,
                               const float* __restrict__ Wq,
                               const float* __restrict__ Wk,
                               const float* __restrict__ Wv,
                               const float* __restrict__ Wo,
                               int nX4, int nW4) {
    int i = blockIdx.x * blockDim.x + threadIdx.x;
    int total = nX4 + 4 * nW4;
    if (i >= total) return;
    const float* src; __half* dst; int off;
    if (i < nX4) { src = X; dst = g_xh; off = i; }
    else {
        int j = i - nX4;
        int wsel = j / nW4;
        off = j - wsel * nW4;
        src = (wsel == 0) ? Wq : (wsel == 1) ? Wk : (wsel == 2) ? Wv : Wo;
        dst = (wsel == 0) ? g_wqh : (wsel == 1) ? g_wkh : (wsel == 2) ? g_wvh : g_woh;
    }
    float4 v = ((const float4*)src)[off];
    __half2 h01 = __floats2half2_rn(v.x, v.y);
    __half2 h23 = __floats2half2_rn(v.z, v.w);
    uint2 o;
    o.x = *(uint32_t*)&h01;
    o.y = *(uint32_t*)&h23;
    ((uint2*)dst)[off] = o;
}

// ---------------- RoPE table (fp64 range reduction only) ------------------------
__global__ void rope_table_kernel() {
    int i = blockIdx.x * blockDim.x + threadIdx.x;
    if (i >= T_ * D_) return;
    int t = i / D_, d = i % D_;
    int p = (d < D_/2) ? d : d - D_/2;
    double inv = exp(-(2.0 * p / (double)D_) * log(10000.0));
    double ang = fmod((double)t * inv, 6.283185307179586476925);
    float a = (float)ang;
    g_cos[i] = __cosf(a);
    g_sin[i] = __sinf(a);
}

// ---------------- fused QKV projection + bias + RoPE (fp16 mma) -----------------
// grid: (BT/128, H, 3)  block: 128 (4 warps). Tile: 128 x 48, k-chunk 64.
struct QkvSmem { __half As[2][128][72]; __half Bs[2][48][72]; };
#define QKV_SMEM_BYTES ((int)sizeof(QkvSmem))

__global__ __launch_bounds__(128) void qkv_proj_kernel(
    const float* __restrict__ bq, const float* __restrict__ bk,
    const float* __restrict__ bv)
{
    extern __shared__ char smraw[];
    QkvSmem* sm = (QkvSmem*)smraw;

    const int mt = blockIdx.x, h = blockIdx.y, which = blockIdx.z;
    const __half* W   = (which == 0) ? g_wqh : ((which == 1) ? g_wkh : g_wvh);
    const float* bias = (which == 0) ? bq : ((which == 1) ? bk : bv);

    const int tid  = threadIdx.x;
    const int lane = tid & 31;
    const int w    = tid >> 5;
    const int row0 = mt * 128, col0 = h * 48;
    const int g    = lane >> 2;
    const int tg   = lane & 3;

    #pragma unroll
    for (int i = 0; i < 8; i++) {
        int idx = tid + i * 128;
        int r = idx >> 3, c = (idx & 7) * 8;
        cp16((uint32_t)__cvta_generic_to_shared(&sm->As[0][r][c]),
             &g_xh[(size_t)(row0 + r) * C_ + c]);
    }
    #pragma unroll
    for (int i = 0; i < 3; i++) {
        int idx = tid + i * 128;
        int r = idx >> 3, c = (idx & 7) * 8;
        cp16((uint32_t)__cvta_generic_to_shared(&sm->Bs[0][r][c]),
             &W[(size_t)(col0 + r) * C_ + c]);
    }
    cp_commit();

    float acc[2][6][4] = {};

    int it = 0;
    for (int k0 = 0; k0 < C_; k0 += 64, it ^= 1) {
        __syncthreads();
        if (k0 + 64 < C_) {
            #pragma unroll
            for (int i = 0; i < 8; i++) {
                int idx = tid + i * 128;
                int r = idx >> 3, c = (idx & 7) * 8;
                cp16((uint32_t)__cvta_generic_to_shared(&sm->As[it^1][r][c]),
                     &g_xh[(size_t)(row0 + r) * C_ + k0 + 64 + c]);
            }
            #pragma unroll
            for (int i = 0; i < 3; i++) {
                int idx = tid + i * 128;
                int r = idx >> 3, c = (idx & 7) * 8;
                cp16((uint32_t)__cvta_generic_to_shared(&sm->Bs[it^1][r][c]),
                     &W[(size_t)(col0 + r) * C_ + k0 + 64 + c]);
            }
        }
        cp_commit();
        cp_wait<1>();
        __syncthreads();

        #pragma unroll
        for (int ks = 0; ks < 4; ks++) {
            const int ac = ks * 16 + 2 * tg;
            uint32_t a[2][4];
            #pragma unroll
            for (int mi = 0; mi < 2; mi++) {
                int ar = w * 32 + mi * 16 + g;
                a[mi][0] = ldsm_u32(&sm->As[it][ar  ][ac]);
                a[mi][1] = ldsm_u32(&sm->As[it][ar+8][ac]);
                a[mi][2] = ldsm_u32(&sm->As[it][ar  ][ac+8]);
                a[mi][3] = ldsm_u32(&sm->As[it][ar+8][ac+8]);
            }
            #pragma unroll
            for (int nf = 0; nf < 6; nf++) {
                uint32_t bf[2];
                int br = nf * 8 + g;
                bf[0] = ldsm_u32(&sm->Bs[it][br][ac]);
                bf[1] = ldsm_u32(&sm->Bs[it][br][ac+8]);
                mma_f16(acc[0][nf], a[0], bf);
                mma_f16(acc[1][nf], a[1], bf);
            }
        }
    }

    if (which != 2) {
        __half* out = (which == 0) ? g_qh : g_kh;
        #pragma unroll
        for (int mi = 0; mi < 2; mi++) {
            #pragma unroll
            for (int half_ = 0; half_ < 2; half_++) {
                int grow = row0 + w * 32 + mi * 16 + g + half_ * 8;
                int b = grow >> 11;             // T_ = 2048
                int t = grow & (T_ - 1);
                size_t base = ((size_t)((b * H_ + h) * T_) + t) * D_;
                #pragma unroll
                for (int nf = 0; nf < 3; nf++) {
                    int d = nf * 8 + 2 * tg;
                    float c0 = g_cos[t * D_ + d],     s0 = g_sin[t * D_ + d];
                    float c1 = g_cos[t * D_ + d + 1], s1 = g_sin[t * D_ + d + 1];
                    float x1a = acc[mi][nf  ][2*half_+0] + bias[col0 + d];
                    float x1b = acc[mi][nf  ][2*half_+1] + bias[col0 + d + 1];
                    float x2a = acc[mi][nf+3][2*half_+0] + bias[col0 + d + 24];
                    float x2b = acc[mi][nf+3][2*half_+1] + bias[col0 + d + 25];
                    __half2 lo = __floats2half2_rn(x1a * c0 - x2a * s0,
                                                   x1b * c1 - x2b * s1);
                    __half2 hi = __floats2half2_rn(x2a * c0 + x1a * s0,
                                                   x2b * c1 + x1b * s1);
                    *(__half2*)&out[base + d]      = lo;
                    *(__half2*)&out[base + d + 24] = hi;
                }
            }
        }
    } else {
        // V: stage transpose in smem, write [B,H,D,T] coalesced.
        __syncthreads();                 // done with As/Bs
        __half* Ts = (__half*)smraw;     // [48][136] halfs = 13056 B
        const int TP = 136;
        #pragma unroll
        for (int mi = 0; mi < 2; mi++) {
            #pragma unroll
            for (int half_ = 0; half_ < 2; half_++) {
                int tloc = w * 32 + mi * 16 + g + half_ * 8;
                #pragma unroll
                for (int nf = 0; nf < 6; nf++) {
                    int d = nf * 8 + 2 * tg;
                    Ts[ d      * TP + tloc] = __float2half_rn(acc[mi][nf][2*half_+0] + bias[col0 + d]);
                    Ts[(d + 1) * TP + tloc] = __float2half_rn(acc[mi][nf][2*half_+1] + bias[col0 + d + 1]);
                }
            }
        }
        __syncthreads();
        int b = (row0 >> 11);
        int t0 = row0 & (T_ - 1);
        #pragma unroll
        for (int i = 0; i < 6; i++) {
            int idx = tid + i * 128;
            int d = idx >> 4, seg = (idx & 15) * 8;
            uint2 v0 = *(const uint2*)&Ts[d * TP + seg];
            uint2 v1 = *(const uint2*)&Ts[d * TP + seg + 4];
            uint4 v = {v0.x, v0.y, v1.x, v1.y};
            *(uint4*)&g_vh[((size_t)((b * H_ + h) * D_ + d)) * T_ + t0 + seg] = v;
        }
    }
}

// ---------------- flash-style causal attention (fp16 mma, cp.async) -------------
// grid: (T/128, B*H)  block: 128 (4 warps). Q tile 128 rows, warp = 32 rows.
// Fixed-shift softmax; P stays in registers; interleaved S/exp/PV; one barrier
// per iteration. THIS ROUND: __launch_bounds__(128, 4) caps regs at 128 so 4
// CTAs/SM fit (65536 regs / (128 thr * 128 reg) = 4; smem 45.3KB*4 < 228KB).
struct AttnSmem {
    __half Qs[128][56];     // 14336 B
    __half Ks[2][64][56];   // 14336 B
    __half Vt[2][56][72];   // 16128 B  V transposed [d][key]; row 48 = ones
    float  Ms[2][64];       //   512 B
};
#define ATTN_SMEM_BYTES ((int)sizeof(AttnSmem))

__global__ __launch_bounds__(128, 4) void attn_kernel(const float* __restrict__ amask)
{
    extern __shared__ char smraw[];
    AttnSmem* sm = (AttnSmem*)smraw;

    const int qi = gridDim.x - 1 - blockIdx.x;   // 128-row q block, big first
    const int bh = blockIdx.y;
    const int b = bh >> 4;
    const __half* Q = g_qh + (size_t)bh * T_ * D_;
    const __half* K = g_kh + (size_t)bh * T_ * D_;
    const __half* V = g_vh + (size_t)bh * D_ * T_;   // [d][t]

    const int tid  = threadIdx.x;
    const int lane = tid & 31;
    const int w    = tid >> 5;
    const int g    = lane >> 2;
    const int tg   = lane & 3;

    // ones rows for BOTH V stages (rows 48..55; row 48 = 1, rest 0)
    for (int idx = tid; idx < 2 * 8 * 72; idx += 128) {
        int st = idx / (8 * 72);
        int r = 48 + (idx % (8 * 72)) / 72, c = idx % 72;
        sm->Vt[st][r][c] = (r == 48) ? __float2half(1.0f) : __float2half(0.0f);
    }

    // prologue: Q tile + K block 0 + V block 0 (stage 0)
    #pragma unroll
    for (int i = 0; i < 6; i++) {
        int idx = tid + i * 128;
        int r = idx / 6, c = (idx % 6) * 8;
        cp16((uint32_t)__cvta_generic_to_shared(&sm->Qs[r][c]),
             &Q[(size_t)(qi * 128 + r) * D_ + c]);
    }
    #pragma unroll
    for (int i = 0; i < 3; i++) {
        int idx = tid + i * 128;
        int r = idx / 6, c = (idx % 6) * 8;
        cp16((uint32_t)__cvta_generic_to_shared(&sm->Ks[0][r][c]),
             &K[(size_t)r * D_ + c]);
    }
    #pragma unroll
    for (int i = 0; i < 3; i++) {
        int idx = tid + i * 128;
        int d = idx >> 3, c = (idx & 7) * 8;
        cp16((uint32_t)__cvta_generic_to_shared(&sm->Vt[0][d][c]),
             &V[(size_t)d * T_ + c]);
    }
    cp_commit();

    // mask block 0 -> Ms[0]; preload block 1 into msr (kmax >= 1 always)
    float msr = 0.f;
    if (tid < 64) {
        float m0 = amask[b * T_ + tid];
        sm->Ms[0][tid] = (1.0f - m0) * -10000.0f * LOG2E;
        msr = amask[b * T_ + 64 + tid];
    }

    cp_wait<0>();
    __syncthreads();

    // hoist Q fragments (tile-invariant across the key loop)
    uint32_t qf[2][3][4];
    #pragma unroll
    for (int ks3 = 0; ks3 < 3; ks3++) {
        const int ac = ks3 * 16 + 2 * tg;
        #pragma unroll
        for (int mi = 0; mi < 2; mi++) {
            int ar = w * 32 + mi * 16 + g;
            qf[mi][ks3][0] = ldsm_u32(&sm->Qs[ar  ][ac]);
            qf[mi][ks3][1] = ldsm_u32(&sm->Qs[ar+8][ac]);
            qf[mi][ks3][2] = ldsm_u32(&sm->Qs[ar  ][ac+8]);
            qf[mi][ks3][3] = ldsm_u32(&sm->Qs[ar+8][ac+8]);
        }
    }

    float o[2][7][4] = {};                           // nf 6 = l accumulator
    const float scale = rsqrtf((float)D_) * LOG2E;   // log2-domain
    const int kmax = 2 * qi + 1;

    for (int kj = 0; kj <= kmax; kj++) {
        const int s = kj & 1;

        // prefetch next K/V + next-mask write (stage s^1 free since iter kj-1)
        if (kj < kmax) {
            #pragma unroll
            for (int i = 0; i < 3; i++) {
                int idx = tid + i * 128;
                int r = idx / 6, c = (idx % 6) * 8;
                cp16((uint32_t)__cvta_generic_to_shared(&sm->Ks[s^1][r][c]),
                     &K[(size_t)((kj + 1) * 64 + r) * D_ + c]);
            }
            #pragma unroll
            for (int i = 0; i < 3; i++) {
                int idx = tid + i * 128;
                int d = idx >> 3, c = (idx & 7) * 8;
                cp16((uint32_t)__cvta_generic_to_shared(&sm->Vt[s^1][d][c]),
                     &V[(size_t)d * T_ + (kj + 1) * 64 + c]);
            }
            if (tid < 64) sm->Ms[s^1][tid] = (1.0f - msr) * -10000.0f * LOG2E;
            cp_commit();
            if (kj + 1 < kmax && tid < 64) msr = amask[b * T_ + (kj + 2) * 64 + tid];
        }

        const bool need_causal = (kj >= kmax - 1);
        const int qrow0 = qi * 128 + w * 32 + g;     // mi=0 row; +16 for mi=1

        // ---- interleaved: per column-pair {S-mma x6, exp, PV-mma x14} ----
        #pragma unroll
        for (int kp = 0; kp < 4; kp++) {
            float sS4[2][2][4] = {};
            #pragma unroll
            for (int j = 0; j < 2; j++) {
                const int nf = 2 * kp + j;
                #pragma unroll
                for (int ks3 = 0; ks3 < 3; ks3++) {
                    uint32_t bf[2];
                    const int ac = ks3 * 16 + 2 * tg;
                    int br = nf * 8 + g;
                    bf[0] = ldsm_u32(&sm->Ks[s][br][ac]);
                    bf[1] = ldsm_u32(&sm->Ks[s][br][ac+8]);
                    mma_f16(sS4[0][j], qf[0][ks3], bf);
                    mma_f16(sS4[1][j], qf[1][ks3], bf);
                }
            }
            // exp -> PV A-fragment registers
            uint32_t a[2][4];
            #pragma unroll
            for (int mi = 0; mi < 2; mi++) {
                const int qr0 = qrow0 + mi * 16;
                #pragma unroll
                for (int j = 0; j < 2; j++) {
                    const int nf = 2 * kp + j;
                    float ma0 = sm->Ms[s][nf * 8 + 2 * tg];
                    float ma1 = sm->Ms[s][nf * 8 + 2 * tg + 1];
                    float v00 = sS4[mi][j][0] * scale + ma0;
                    float v01 = sS4[mi][j][1] * scale + ma1;
                    float v10 = sS4[mi][j][2] * scale + ma0;
                    float v11 = sS4[mi][j][3] * scale + ma1;
                    if (need_causal) {
                        int kc = kj * 64 + nf * 8 + 2 * tg;
                        v00 = (kc     > qr0    ) ? -INFINITY : v00;
                        v01 = (kc + 1 > qr0    ) ? -INFINITY : v01;
                        v10 = (kc     > qr0 + 8) ? -INFINITY : v10;
                        v11 = (kc + 1 > qr0 + 8) ? -INFINITY : v11;
                    }
                    a[mi][2*j+0] = exp2_f16x2(v00, v01);
                    a[mi][2*j+1] = exp2_f16x2(v10, v11);
                }
            }
            // PV for this key chunk (nf 6 accumulates l via ones-row 48)
            const int ac = kp * 16 + 2 * tg;
            #pragma unroll
            for (int nf = 0; nf < 7; nf++) {
                uint32_t bf[2];
                int vr = nf * 8 + g;
                bf[0] = ldsm_u32(&sm->Vt[s][vr][ac]);
                bf[1] = ldsm_u32(&sm->Vt[s][vr][ac+8]);
                mma_f16(o[0][nf], a[0], bf);
                mma_f16(o[1][nf], a[1], bf);
            }
        }

        cp_wait<0>();      // group issued at top of this iter complete
        __syncthreads();   // all warps done with stage s; Ms[s^1] visible
    }

    // ---- normalize + write ctx [B,T,C] fp16; l lives in o[mi][6] col 48 (tg=0) --
    const int h = bh & 15;
    #pragma unroll
    for (int mi = 0; mi < 2; mi++) {
        float l0 = __shfl_sync(0xffffffffu, o[mi][6][0], lane & 28);
        float l1 = __shfl_sync(0xffffffffu, o[mi][6][2], lane & 28);
        float invl[2] = {1.0f / l0, 1.0f / l1};
        #pragma unroll
        for (int half_ = 0; half_ < 2; half_++) {
            int t = qi * 128 + w * 32 + mi * 16 + g + half_ * 8;
            size_t base = (size_t)(b * T_ + t) * C_ + h * D_;
            #pragma unroll
            for (int nf = 0; nf < 6; nf++) {
                int d = nf * 8 + 2 * tg;
                *(__half2*)&g_ctx[base + d] =
                    __floats2half2_rn(o[mi][nf][2*half_+0] * invl[half_],
                                      o[mi][nf][2*half_+1] * invl[half_]);
            }
        }
    }
}

// ---------------- output projection: out = ctx @ Wo^T + bo (fp16 mma) -----------
// grid: (BT/128, C/64)  block: 128 (4 warps). Tile 128x64, k-chunk 64.
struct OutSmem { __half As[2][128][72]; __half Bs[2][64][72]; };
#define OUT_SMEM_BYTES ((int)sizeof(OutSmem))

__global__ __launch_bounds__(128) void out_proj_kernel(
    const float* __restrict__ bo, float* __restrict__ out)
{
    extern __shared__ char smraw[];
    OutSmem* sm = (OutSmem*)smraw;

    const int mt = blockIdx.x, nt = blockIdx.y;
    const int tid  = threadIdx.x;
    const int lane = tid & 31;
    const int w    = tid >> 5;
    const int g    = lane >> 2;
    const int tg   = lane & 3;
    const int row0 = mt * 128, col0 = nt * 64;

    #pragma unroll
    for (int i = 0; i < 8; i++) {
        int idx = tid + i * 128;
        int r = idx >> 3, c = (idx & 7) * 8;
        cp16((uint32_t)__cvta_generic_to_shared(&sm->As[0][r][c]),
             &g_ctx[(size_t)(row0 + r) * C_ + c]);
    }
    #pragma unroll
    for (int i = 0; i < 4; i++) {
        int idx = tid + i * 128;
        int r = idx >> 3, c = (idx & 7) * 8;
        cp16((uint32_t)__cvta_generic_to_shared(&sm->Bs[0][r][c]),
             &g_woh[(size_t)(col0 + r) * C_ + c]);
    }
    cp_commit();

    float acc[2][8][4] = {};

    int it = 0;
    for (int k0 = 0; k0 < C_; k0 += 64, it ^= 1) {
        __syncthreads();
        if (k0 + 64 < C_) {
            #pragma unroll
            for (int i = 0; i < 8; i++) {
                int idx = tid + i * 128;
                int r = idx >> 3, c = (idx & 7) * 8;
                cp16((uint32_t)__cvta_generic_to_shared(&sm->As[it^1][r][c]),
                     &g_ctx[(size_t)(row0 + r) * C_ + k0 + 64 + c]);
            }
            #pragma unroll
            for (int i = 0; i < 4; i++) {
                int idx = tid + i * 128;
                int r = idx >> 3, c = (idx & 7) * 8;
                cp16((uint32_t)__cvta_generic_to_shared(&sm->Bs[it^1][r][c]),
                     &g_woh[(size_t)(col0 + r) * C_ + k0 + 64 + c]);
            }
        }
        cp_commit();
        cp_wait<1>();
        __syncthreads();

        #pragma unroll
        for (int ks = 0; ks < 4; ks++) {
            const int ac = ks * 16 + 2 * tg;
            uint32_t a[2][4];
            #pragma unroll
            for (int mi = 0; mi < 2; mi++) {
                int ar = w * 32 + mi * 16 + g;
                a[mi][0] = ldsm_u32(&sm->As[it][ar  ][ac]);
                a[mi][1] = ldsm_u32(&sm->As[it][ar+8][ac]);
                a[mi][2] = ldsm_u32(&sm->As[it][ar  ][ac+8]);
                a[mi][3] = ldsm_u32(&sm->As[it][ar+8][ac+8]);
            }
            #pragma unroll
            for (int nf = 0; nf < 8; nf++) {
                uint32_t bf[2];
                int br = nf * 8 + g;
                bf[0] = ldsm_u32(&sm->Bs[it][br][ac]);
                bf[1] = ldsm_u32(&sm->Bs[it][br][ac+8]);
                mma_f16(acc[0][nf], a[0], bf);
                mma_f16(acc[1][nf], a[1], bf);
            }
        }
    }

    #pragma unroll
    for (int mi = 0; mi < 2; mi++) {
        #pragma unroll
        for (int half_ = 0; half_ < 2; half_++) {
            int r = row0 + w * 32 + mi * 16 + g + half_ * 8;
            #pragma unroll
            for (int nf = 0; nf < 8; nf++) {
                int c = col0 + nf * 8 + 2 * tg;
                float2 v;
                v.x = acc[mi][nf][2*half_+0] + bo[c];
                v.y = acc[mi][nf][2*half_+1] + bo[c + 1];
                *(float2*)&out[(size_t)r * C_ + c] = v;
            }
        }
    }
}

// ---------------- launch -------------------------------------------------------
extern "C" void kernel_launch(void* const* d_in, const int* in_sizes, int n_in,
                              void* d_out, int out_size)
{
    const float* X     = (const float*)d_in[0];
    const float* amask = (const float*)d_in[1];
    const float* Wq    = (const float*)d_in[2];
    const float* bq    = (const float*)d_in[3];
    const float* Wk    = (const float*)d_in[4];
    const float* bk    = (const float*)d_in[5];
    const float* Wv    = (const float*)d_in[6];
    const float* bv    = (const float*)d_in[7];
    const float* Wo    = (const float*)d_in[8];
    const float* bo    = (const float*)d_in[9];
    float* out = (float*)d_out;

    cudaFuncSetAttribute(attn_kernel, cudaFuncAttributeMaxDynamicSharedMemorySize,
                         ATTN_SMEM_BYTES);
    cudaFuncSetAttribute(qkv_proj_kernel, cudaFuncAttributeMaxDynamicSharedMemorySize,
                         QKV_SMEM_BYTES);
    cudaFuncSetAttribute(out_proj_kernel, cudaFuncAttributeMaxDynamicSharedMemorySize,
                         OUT_SMEM_BYTES);

    const int nX4 = (B_ * T_ * C_) / 4;
    const int nW4 = (C_ * C_) / 4;
    const int nTot = nX4 + 4 * nW4;

    rope_table_kernel<<<(T_ * D_ + 255) / 256, 256>>>();
    f2h_all_kernel<<<(nTot + 255) / 256, 256>>>(X, Wq, Wk, Wv, Wo, nX4, nW4);
    qkv_proj_kernel<<<dim3((B_ * T_) / 128, H_, 3), 128, QKV_SMEM_BYTES>>>(bq, bk, bv);
    attn_kernel<<<dim3(T_ / 128, B_ * H_), 128, ATTN_SMEM_BYTES>>>(amask);
    out_proj_kernel<<<dim3((B_ * T_) / 128, C_ / 64), 128, OUT_SMEM_BYTES>>>(bo, out);
}